// round 12
// baseline (speedup 1.0000x reference)
#include <cuda_runtime.h>
#include <cuda_fp16.h>
#include <math.h>
#include <stdint.h>

#define SEQ    2048
#define DMODEL 2048
#define NH     32
#define NKV    8
#define HD     64
#define KVD    (NKV*HD)   // 512

// -------------------- scratch (no allocs allowed) --------------------
__device__ float g_cos[SEQ*(HD/2)];
__device__ float g_sin[SEQ*(HD/2)];

__device__ __half g_xhi[SEQ*DMODEL];
__device__ __half g_wqhi[DMODEL*DMODEL];
__device__ __half g_wkhi[KVD*DMODEL];
__device__ __half g_wvhi[KVD*DMODEL];
__device__ __half g_wohi[DMODEL*DMODEL];
__device__ __half g_chi[SEQ*DMODEL];
__device__ __half g_qh[SEQ*DMODEL];
__device__ __half g_kh[SEQ*KVD];
__device__ __half g_vh[SEQ*KVD];

// ==================== helpers ====================
__device__ __forceinline__ uint32_t smem_u32(const void* p) {
    uint32_t a;
    asm("{ .reg .u64 t; cvta.to.shared.u64 t, %1; cvt.u32.u64 %0, t; }"
        : "=r"(a) : "l"(p));
    return a;
}

#define CP_ASYNC16(dst, src) \
    asm volatile("cp.async.cg.shared.global [%0], [%1], 16;" :: "r"(dst), "l"(src) : "memory")
#define CP_COMMIT() asm volatile("cp.async.commit_group;" ::: "memory")
#define CP_WAIT_0() asm volatile("cp.async.wait_group 0;" ::: "memory")

#define LDSM4(r0, r1, r2, r3, addr) \
    asm volatile("ldmatrix.sync.aligned.m8n8.x4.shared.b16 {%0,%1,%2,%3}, [%4];" \
        : "=r"(r0), "=r"(r1), "=r"(r2), "=r"(r3) : "r"(addr))

#define LDSM4T(r0, r1, r2, r3, addr) \
    asm volatile("ldmatrix.sync.aligned.m8n8.x4.trans.shared.b16 {%0,%1,%2,%3}, [%4];" \
        : "=r"(r0), "=r"(r1), "=r"(r2), "=r"(r3) : "r"(addr))

#define MMA16816(d, a, b0, b1) \
    asm volatile("mma.sync.aligned.m16n8k16.row.col.f32.f16.f16.f32 " \
        "{%0,%1,%2,%3}, {%4,%5,%6,%7}, {%8,%9}, {%0,%1,%2,%3};" \
        : "+f"((d)[0]), "+f"((d)[1]), "+f"((d)[2]), "+f"((d)[3]) \
        : "r"((a)[0]), "r"((a)[1]), "r"((a)[2]), "r"((a)[3]), "r"(b0), "r"(b1))

// ==================== fp32 -> fp16 converts + rope table (one launch) ====================
__device__ __forceinline__ void conv4(const float* __restrict__ src,
                                      __half* __restrict__ hi, int i) {
    float4 x = ((const float4*)src)[i];
    __half2* hp = (__half2*)(hi + i * 4);
    hp[0] = __half2(__float2half_rn(x.x), __float2half_rn(x.y));
    hp[1] = __half2(__float2half_rn(x.z), __float2half_rn(x.w));
}

#define WQ4 (DMODEL*DMODEL/4)
#define WK4 (KVD*DMODEL/4)
#define X4  (SEQ*DMODEL/4)
#define CONV_END (2*WQ4 + 2*WK4 + X4)
#define TOTAL_PREP (CONV_END + SEQ*32)
__global__ void prep_kernel(const float* __restrict__ Wq, const float* __restrict__ Wk,
                            const float* __restrict__ Wv, const float* __restrict__ Wo,
                            const float* __restrict__ x, const int* __restrict__ start_pos,
                            __half* __restrict__ qh, __half* __restrict__ kh,
                            __half* __restrict__ vh, __half* __restrict__ oh,
                            __half* __restrict__ xh) {
    int i = blockIdx.x * blockDim.x + threadIdx.x;
    if (i < WQ4)                     { conv4(Wq, qh, i); return; }
    if (i < WQ4 + WK4)               { conv4(Wk, kh, i - WQ4); return; }
    if (i < WQ4 + 2*WK4)             { conv4(Wv, vh, i - WQ4 - WK4); return; }
    if (i < 2*WQ4 + 2*WK4)           { conv4(Wo, oh, i - WQ4 - 2*WK4); return; }
    if (i < CONV_END)                { conv4(x, xh, i - 2*WQ4 - 2*WK4); return; }
    if (i >= TOTAL_PREP) return;
    // rope table
    int idx = i - CONV_END;
    int t = idx >> 5, j = idx & 31;
    const double PI = 3.14159265358979323846;
    double e = (double)(2 * j) / 64.0;
    double invf = pow(500000.0, -e);
    double wavelen = 2.0 * PI / invf;
    double inv;
    if (wavelen > 8192.0)      inv = invf / 32.0;
    else if (wavelen < 2048.0) inv = invf;
    else {
        double smooth = (8192.0 / wavelen - 1.0) / 3.0;
        inv = (1.0 - smooth) * (invf / 32.0) + smooth * invf;
    }
    float angle = (float)(start_pos[0] + t) * (float)inv;
    g_cos[idx] = (float)cos((double)angle);
    g_sin[idx] = (float)sin((double)angle);
}

// ==================== QKV GEMM with fused RoPE/convert epilogue ====================
// 1-term fp16, full K=2048. Output fp16 (q,k roped; v plain).
#define BK 32
#define ASTRH 40
#define TILEB (128 * ASTRH * 2)     // 10240 bytes
#define QKV_SMEM (128 * 130 * 4)    // epilogue staging 66560 > pipeline 40960

__global__ void __launch_bounds__(256, 2) gemm_qkv(
    const __half* __restrict__ Ahi,
    const __half* __restrict__ Bq, const __half* __restrict__ Bk,
    const __half* __restrict__ Bv,
    __half* __restrict__ Oq, __half* __restrict__ Ok, __half* __restrict__ Ov) {
    extern __shared__ __half gsm[];
    const int bx = blockIdx.x;
    const __half* Bh; __half* Out; int Nc, bnl, mode;
    if (bx < 16)      { Bh = Bq; Out = Oq; Nc = DMODEL; bnl = bx * 128;        mode = 0; }
    else if (bx < 20) { Bh = Bk; Out = Ok; Nc = KVD;    bnl = (bx - 16) * 128; mode = 1; }
    else              { Bh = Bv; Out = Ov; Nc = KVD;    bnl = (bx - 20) * 128; mode = 2; }
    const int K = DMODEL;

    const int tid = threadIdx.x;
    const int wid = tid >> 5, lane = tid & 31;
    const int wm = (wid & 1) * 64;
    const int wn = (wid >> 1) * 32;
    const int bm = blockIdx.y * 128;
    const int lr = lane & 15, lc = lane >> 4;

    uint32_t sbu = smem_u32(gsm);
    const int r0_ = tid >> 2, r1_ = r0_ + 64;
    const int pp = (tid & 3) * 8;

    float acc[4][4][4];
#pragma unroll
    for (int a = 0; a < 4; a++)
#pragma unroll
        for (int b = 0; b < 4; b++)
#pragma unroll
            for (int c = 0; c < 4; c++) acc[a][b][c] = 0.f;

#define LOADCHUNK(st, k0) do {                                                  \
    uint32_t _b = sbu + (st) * (2 * TILEB);                                     \
    CP_ASYNC16(_b + (r0_ * ASTRH + pp) * 2,                                     \
               Ahi + (size_t)(bm + r0_) * K + (k0) + pp);                       \
    CP_ASYNC16(_b + (r1_ * ASTRH + pp) * 2,                                     \
               Ahi + (size_t)(bm + r1_) * K + (k0) + pp);                       \
    CP_ASYNC16(_b + TILEB + (r0_ * ASTRH + pp) * 2,                             \
               Bh + (size_t)(bnl + r0_) * K + (k0) + pp);                       \
    CP_ASYNC16(_b + TILEB + (r1_ * ASTRH + pp) * 2,                             \
               Bh + (size_t)(bnl + r1_) * K + (k0) + pp);                       \
} while (0)

    const int kiters = K / BK;
    LOADCHUNK(0, 0);
    CP_COMMIT();

    for (int i = 0; i < kiters; i++) {
        int s = i & 1;
        CP_WAIT_0();
        __syncthreads();
        if (i + 1 < kiters) {
            LOADCHUNK(s ^ 1, (i + 1) * BK);
            CP_COMMIT();
        }

        uint32_t base = sbu + s * (2 * TILEB);
#pragma unroll
        for (int k16 = 0; k16 < 2; k16++) {
            int koff16 = k16 * 16 + lc * 8;
            uint32_t aH[4][4], bH[2][4];
#pragma unroll
            for (int mt = 0; mt < 4; mt++) {
                uint32_t adr = base + ((wm + mt * 16 + lr) * ASTRH + koff16) * 2;
                LDSM4(aH[mt][0], aH[mt][1], aH[mt][2], aH[mt][3], adr);
            }
#pragma unroll
            for (int p = 0; p < 2; p++) {
                uint32_t adr = base + TILEB + ((wn + p * 16 + lr) * ASTRH + koff16) * 2;
                LDSM4(bH[p][0], bH[p][1], bH[p][2], bH[p][3], adr);
            }
#pragma unroll
            for (int mt = 0; mt < 4; mt++)
#pragma unroll
                for (int nt = 0; nt < 4; nt++) {
                    int p = nt >> 1, w = nt & 1;
                    MMA16816(acc[mt][nt], aH[mt], bH[p][w], bH[p][w + 2]);
                }
        }
    }

    // ---- fused epilogue: acc -> smem fp32 -> rope/convert -> fp16 global ----
    __syncthreads();
    float* se = (float*)gsm;    // 128 x 130
    int er = lane >> 2, ec = (lane & 3) * 2;
#pragma unroll
    for (int mt = 0; mt < 4; mt++)
#pragma unroll
        for (int nt = 0; nt < 4; nt++) {
            int r = wm + mt * 16 + er;
            int c = wn + nt * 8 + ec;
            se[r * 130 + c]           = acc[mt][nt][0];
            se[r * 130 + c + 1]       = acc[mt][nt][1];
            se[(r + 8) * 130 + c]     = acc[mt][nt][2];
            se[(r + 8) * 130 + c + 1] = acc[mt][nt][3];
        }
    __syncthreads();

    if (mode < 2) {   // rope (q or k): heads are 64 wide, 2 heads per 128-tile
#pragma unroll
        for (int l = 0; l < 16; l++) {
            int p = tid + l * 256;       // 0..4095 (pairs of rope-pairs)
            int r = p >> 5;              // 0..127
            int q2 = p & 31;
            int head = q2 >> 4;          // 0..1
            int j = (q2 & 15) * 2;       // 0,2,..,30
            int t = bm + r;
            float c0 = g_cos[t * 32 + j],     s0 = g_sin[t * 32 + j];
            float c1 = g_cos[t * 32 + j + 1], s1 = g_sin[t * 32 + j + 1];
            int cc = head * 64 + j;
            float x1a = se[r * 130 + cc],      x1b = se[r * 130 + cc + 1];
            float x2a = se[r * 130 + cc + 32], x2b = se[r * 130 + cc + 33];
            __half2 y1 = __floats2half2_rn(x1a * c0 - x2a * s0, x1b * c1 - x2b * s1);
            __half2 y2 = __floats2half2_rn(x2a * c0 + x1a * s0, x2b * c1 + x1b * s1);
            size_t rowb = (size_t)t * Nc + bnl + cc;
            *(__half2*)&Out[rowb]      = y1;
            *(__half2*)&Out[rowb + 32] = y2;
        }
    } else {          // v: plain convert
#pragma unroll
        for (int l = 0; l < 16; l++) {
            int p = tid + l * 256;       // 0..4095, 4 cols each
            int r = p >> 5;
            int cc = (p & 31) * 4;
            float a0 = se[r * 130 + cc],     a1 = se[r * 130 + cc + 1];
            float a2 = se[r * 130 + cc + 2], a3 = se[r * 130 + cc + 3];
            size_t rowb = (size_t)(bm + r) * Nc + bnl + cc;
            *(__half2*)&Out[rowb]     = __floats2half2_rn(a0, a1);
            *(__half2*)&Out[rowb + 2] = __floats2half2_rn(a2, a3);
        }
    }
}

// ==================== O-projection GEMM (fp32 out) ====================
#define GSMEM (TILEB * 4)           // 2 stages x 2 tiles = 40960

__global__ void __launch_bounds__(256, 2) gemm_o(
    const __half* __restrict__ Ahi,
    const __half* __restrict__ Bh,
    float* __restrict__ C, int N, int K) {
    extern __shared__ __half gsm[];
    const int bnl = blockIdx.x * 128;

    const int tid = threadIdx.x;
    const int wid = tid >> 5, lane = tid & 31;
    const int wm = (wid & 1) * 64;
    const int wn = (wid >> 1) * 32;
    const int bm = blockIdx.y * 128;
    const int lr = lane & 15, lc = lane >> 4;

    uint32_t sbu = smem_u32(gsm);
    const int r0_ = tid >> 2, r1_ = r0_ + 64;
    const int pp = (tid & 3) * 8;

    float acc[4][4][4];
#pragma unroll
    for (int a = 0; a < 4; a++)
#pragma unroll
        for (int b = 0; b < 4; b++)
#pragma unroll
            for (int c = 0; c < 4; c++) acc[a][b][c] = 0.f;

    const int kiters = K / BK;
    LOADCHUNK(0, 0);
    CP_COMMIT();

    for (int i = 0; i < kiters; i++) {
        int s = i & 1;
        CP_WAIT_0();
        __syncthreads();
        if (i + 1 < kiters) {
            LOADCHUNK(s ^ 1, (i + 1) * BK);
            CP_COMMIT();
        }

        uint32_t base = sbu + s * (2 * TILEB);
#pragma unroll
        for (int k16 = 0; k16 < 2; k16++) {
            int koff16 = k16 * 16 + lc * 8;
            uint32_t aH[4][4], bH[2][4];
#pragma unroll
            for (int mt = 0; mt < 4; mt++) {
                uint32_t adr = base + ((wm + mt * 16 + lr) * ASTRH + koff16) * 2;
                LDSM4(aH[mt][0], aH[mt][1], aH[mt][2], aH[mt][3], adr);
            }
#pragma unroll
            for (int p = 0; p < 2; p++) {
                uint32_t adr = base + TILEB + ((wn + p * 16 + lr) * ASTRH + koff16) * 2;
                LDSM4(bH[p][0], bH[p][1], bH[p][2], bH[p][3], adr);
            }
#pragma unroll
            for (int mt = 0; mt < 4; mt++)
#pragma unroll
                for (int nt = 0; nt < 4; nt++) {
                    int p = nt >> 1, w = nt & 1;
                    MMA16816(acc[mt][nt], aH[mt], bH[p][w], bH[p][w + 2]);
                }
        }
    }

    int er = lane >> 2, ec = (lane & 3) * 2;
#pragma unroll
    for (int mt = 0; mt < 4; mt++) {
#pragma unroll
        for (int nt = 0; nt < 4; nt++) {
            int r = bm + wm + mt * 16 + er;
            int c = bnl + wn + nt * 8 + ec;
            *(float2*)&C[(size_t)r * N + c]       = make_float2(acc[mt][nt][0], acc[mt][nt][1]);
            *(float2*)&C[(size_t)(r + 8) * N + c] = make_float2(acc[mt][nt][2], acc[mt][nt][3]);
        }
    }
}

// ==================== HMMA flash attention (1-term) ====================
#define FATR 72
#define FTILE (64 * FATR * 2)
#define FLASH_SMEM (FTILE * 5)   // Qh + 2 stages x (Kh, Vh)

__global__ void __launch_bounds__(128) flash_hmma(
    const __half* __restrict__ qhi,
    const __half* __restrict__ khi,
    const __half* __restrict__ vhi,
    __half* __restrict__ chi) {
    extern __shared__ __half fsm[];
    const int h  = blockIdx.x;
    const int qb = gridDim.y - 1 - blockIdx.y;
    const int g  = h >> 2;
    const int tid = threadIdx.x;
    const int wid = tid >> 5, lane = tid & 31;
    const int wm = wid * 16;
    const int er = lane >> 2, ec = (lane & 3) * 2;
    const int lr = lane & 15, lc = lane >> 4;

    uint32_t sb = smem_u32(fsm);
    uint32_t sQh = sb;

#pragma unroll
    for (int l = 0; l < 4; l++) {
        int c = tid + l * 128;
        int row = c >> 3, cc = c & 7;
        size_t off = (size_t)(qb * 64 + row) * DMODEL + h * 64 + cc * 8;
        CP_ASYNC16(sQh + row * FATR * 2 + cc * 16, qhi + off);
    }
#define KV_LOAD(kb_, st_) do {                                                  \
    uint32_t base = sb + FTILE + (st_) * 2 * FTILE;                             \
    _Pragma("unroll")                                                           \
    for (int l = 0; l < 4; l++) {                                               \
        int c = tid + l * 128;                                                  \
        int row = c >> 3, cc = c & 7;                                           \
        size_t off = (size_t)((kb_) * 64 + row) * KVD + g * 64 + cc * 8;        \
        uint32_t d = row * FATR * 2 + cc * 16;                                  \
        CP_ASYNC16(base + d, khi + off);                                        \
        CP_ASYNC16(base + FTILE + d, vhi + off);                                \
    }                                                                           \
} while (0)

    KV_LOAD(0, 0);
    CP_COMMIT();

    uint32_t aQh[4][4];
    float oacc[8][4];
    float mi0 = -INFINITY, mi1 = -INFINITY, li0 = 0.f, li1 = 0.f;
#pragma unroll
    for (int nt = 0; nt < 8; nt++)
#pragma unroll
        for (int j = 0; j < 4; j++) oacc[nt][j] = 0.f;

    for (int kb = 0; kb <= qb; kb++) {
        int stage = kb & 1;
        CP_WAIT_0();
        __syncthreads();
        if (kb < qb) {
            KV_LOAD(kb + 1, stage ^ 1);
            CP_COMMIT();
        }

        if (kb == 0) {
#pragma unroll
            for (int k16 = 0; k16 < 4; k16++) {
                uint32_t ah = sQh + ((wm + lr) * FATR + k16 * 16 + lc * 8) * 2;
                LDSM4(aQh[k16][0], aQh[k16][1], aQh[k16][2], aQh[k16][3], ah);
            }
        }

        uint32_t base = sb + FTILE + stage * 2 * FTILE;
        uint32_t sKh = base, sVh = base + FTILE;

        float sacc[8][4];
#pragma unroll
        for (int nt = 0; nt < 8; nt++)
#pragma unroll
            for (int j = 0; j < 4; j++) sacc[nt][j] = 0.f;

#pragma unroll
        for (int k16 = 0; k16 < 4; k16++) {
            uint32_t bh[4][4];
#pragma unroll
            for (int p = 0; p < 4; p++) {
                uint32_t adr = sKh + ((p * 16 + lr) * FATR + k16 * 16 + lc * 8) * 2;
                LDSM4(bh[p][0], bh[p][1], bh[p][2], bh[p][3], adr);
            }
#pragma unroll
            for (int nt = 0; nt < 8; nt++) {
                int p = nt >> 1, w = nt & 1;
                MMA16816(sacc[nt], aQh[k16], bh[p][w], bh[p][w + 2]);
            }
        }

        if (kb == qb) {
#pragma unroll
            for (int nt = 0; nt < 8; nt++) {
                int c0 = nt * 8 + ec;
                sacc[nt][0] = (c0     <= wm + er)     ? sacc[nt][0] * 0.125f : -INFINITY;
                sacc[nt][1] = (c0 + 1 <= wm + er)     ? sacc[nt][1] * 0.125f : -INFINITY;
                sacc[nt][2] = (c0     <= wm + er + 8) ? sacc[nt][2] * 0.125f : -INFINITY;
                sacc[nt][3] = (c0 + 1 <= wm + er + 8) ? sacc[nt][3] * 0.125f : -INFINITY;
            }
        } else {
#pragma unroll
            for (int nt = 0; nt < 8; nt++)
#pragma unroll
                for (int j = 0; j < 4; j++) sacc[nt][j] *= 0.125f;
        }

        float mx0 = -INFINITY, mx1 = -INFINITY;
#pragma unroll
        for (int nt = 0; nt < 8; nt++) {
            mx0 = fmaxf(mx0, fmaxf(sacc[nt][0], sacc[nt][1]));
            mx1 = fmaxf(mx1, fmaxf(sacc[nt][2], sacc[nt][3]));
        }
#pragma unroll
        for (int off = 1; off < 4; off <<= 1) {
            mx0 = fmaxf(mx0, __shfl_xor_sync(0xffffffffu, mx0, off));
            mx1 = fmaxf(mx1, __shfl_xor_sync(0xffffffffu, mx1, off));
        }
        float mn0 = fmaxf(mi0, mx0), mn1 = fmaxf(mi1, mx1);
        float sum0 = 0.f, sum1 = 0.f;
#pragma unroll
        for (int nt = 0; nt < 8; nt++) {
            sacc[nt][0] = __expf(sacc[nt][0] - mn0);
            sacc[nt][1] = __expf(sacc[nt][1] - mn0);
            sacc[nt][2] = __expf(sacc[nt][2] - mn1);
            sacc[nt][3] = __expf(sacc[nt][3] - mn1);
            sum0 += sacc[nt][0] + sacc[nt][1];
            sum1 += sacc[nt][2] + sacc[nt][3];
        }
#pragma unroll
        for (int off = 1; off < 4; off <<= 1) {
            sum0 += __shfl_xor_sync(0xffffffffu, sum0, off);
            sum1 += __shfl_xor_sync(0xffffffffu, sum1, off);
        }
        float sc0 = __expf(mi0 - mn0), sc1 = __expf(mi1 - mn1);
        li0 = li0 * sc0 + sum0; li1 = li1 * sc1 + sum1;
        mi0 = mn0; mi1 = mn1;
#pragma unroll
        for (int nt = 0; nt < 8; nt++) {
            oacc[nt][0] *= sc0; oacc[nt][1] *= sc0;
            oacc[nt][2] *= sc1; oacc[nt][3] *= sc1;
        }

#pragma unroll
        for (int k16 = 0; k16 < 4; k16++) {
            uint32_t ph[4];
#pragma unroll
            for (int half16 = 0; half16 < 2; half16++) {
                int st = 2 * k16 + half16;
                __half2 h01 = __floats2half2_rn(sacc[st][0], sacc[st][1]);
                __half2 h23 = __floats2half2_rn(sacc[st][2], sacc[st][3]);
                ph[half16 * 2]     = *(uint32_t*)&h01;
                ph[half16 * 2 + 1] = *(uint32_t*)&h23;
            }
            uint32_t bvh[4][4];
#pragma unroll
            for (int p = 0; p < 4; p++) {
                uint32_t adr = sVh + ((k16 * 16 + lr) * FATR + p * 16 + lc * 8) * 2;
                LDSM4T(bvh[p][0], bvh[p][1], bvh[p][2], bvh[p][3], adr);
            }
#pragma unroll
            for (int nt = 0; nt < 8; nt++) {
                int p = nt >> 1, w = (nt & 1) * 2;
                MMA16816(oacc[nt], ph, bvh[p][w], bvh[p][w + 1]);
            }
        }
    }

    float inv0 = 1.0f / li0, inv1 = 1.0f / li1;
    int r0g = qb * 64 + wm + er, r1g = r0g + 8;
#pragma unroll
    for (int nt = 0; nt < 8; nt++) {
        int c = h * 64 + nt * 8 + ec;
        __half2 h0 = __floats2half2_rn(oacc[nt][0] * inv0, oacc[nt][1] * inv0);
        __half2 h1 = __floats2half2_rn(oacc[nt][2] * inv1, oacc[nt][3] * inv1);
        *(__half2*)&chi[(size_t)r0g * DMODEL + c] = h0;
        *(__half2*)&chi[(size_t)r1g * DMODEL + c] = h1;
    }
}

// -------------------- launch --------------------
extern "C" void kernel_launch(void* const* d_in, const int* in_sizes, int n_in,
                              void* d_out, int out_size) {
    const float* x  = (const float*)d_in[0];
    const float* Wq = (const float*)d_in[1];
    const float* Wk = (const float*)d_in[2];
    const float* Wv = (const float*)d_in[3];
    const float* Wo = (const float*)d_in[4];
    const int* start_pos = (const int*)d_in[5];
    float* out = (float*)d_out;

    __half *xhi, *wqhi, *wkhi, *wvhi, *wohi;
    __half *chi, *qh, *kh, *vh;
    cudaGetSymbolAddress((void**)&xhi, g_xhi);
    cudaGetSymbolAddress((void**)&wqhi, g_wqhi);
    cudaGetSymbolAddress((void**)&wkhi, g_wkhi);
    cudaGetSymbolAddress((void**)&wvhi, g_wvhi);
    cudaGetSymbolAddress((void**)&wohi, g_wohi);
    cudaGetSymbolAddress((void**)&chi, g_chi);
    cudaGetSymbolAddress((void**)&qh, g_qh);
    cudaGetSymbolAddress((void**)&kh, g_kh);
    cudaGetSymbolAddress((void**)&vh, g_vh);

    cudaFuncSetAttribute(gemm_qkv, cudaFuncAttributeMaxDynamicSharedMemorySize, QKV_SMEM);
    cudaFuncSetAttribute(gemm_o, cudaFuncAttributeMaxDynamicSharedMemorySize, GSMEM);
    cudaFuncSetAttribute(flash_hmma, cudaFuncAttributeMaxDynamicSharedMemorySize,
                         FLASH_SMEM);

    // 0: all converts (4 weights + x) + rope table, one launch
    prep_kernel<<<(TOTAL_PREP + 255) / 256, 256>>>(
        Wq, Wk, Wv, Wo, x, start_pos, wqhi, wkhi, wvhi, wohi, xhi);
    // 1: fused Q/K/V projection with RoPE + fp16 epilogue
    gemm_qkv<<<dim3(24, SEQ / 128), 256, QKV_SMEM>>>(
        xhi, wqhi, wkhi, wvhi, qh, kh, vh);
    // 2: flash attention (1-term) -> ctx fp16
    flash_hmma<<<dim3(NH, SEQ / 64), 128, FLASH_SMEM>>>(qh, kh, vh, chi);
    // 3: O projection -> fp32 out
    gemm_o<<<dim3(16, SEQ / 128), 256, GSMEM>>>(chi, wohi, out, DMODEL, DMODEL);
}

// round 13
// speedup vs baseline: 1.0015x; 1.0015x over previous
#include <cuda_runtime.h>
#include <cuda_fp16.h>
#include <math.h>
#include <stdint.h>

#define SEQ    2048
#define DMODEL 2048
#define NH     32
#define NKV    8
#define HD     64
#define KVD    (NKV*HD)   // 512

// -------------------- scratch (no allocs allowed) --------------------
__device__ float g_cos[SEQ*(HD/2)];
__device__ float g_sin[SEQ*(HD/2)];

__device__ __half g_xhi[SEQ*DMODEL];
__device__ __half g_wqhi[DMODEL*DMODEL];
__device__ __half g_wkhi[KVD*DMODEL];
__device__ __half g_wvhi[KVD*DMODEL];
__device__ __half g_wohi[DMODEL*DMODEL];
__device__ __half g_chi[SEQ*DMODEL];
__device__ __half g_qh[SEQ*DMODEL];
__device__ __half g_kh[SEQ*KVD];
__device__ __half g_vh[SEQ*KVD];
// fp16 split-K partials
__device__ __half g_qp0[SEQ*DMODEL], g_qp1[SEQ*DMODEL];
__device__ __half g_kp0[SEQ*KVD],    g_kp1[SEQ*KVD];
__device__ __half g_vp0[SEQ*KVD],    g_vp1[SEQ*KVD];

// ==================== helpers ====================
__device__ __forceinline__ uint32_t smem_u32(const void* p) {
    uint32_t a;
    asm("{ .reg .u64 t; cvta.to.shared.u64 t, %1; cvt.u32.u64 %0, t; }"
        : "=r"(a) : "l"(p));
    return a;
}

#define CP_ASYNC16(dst, src) \
    asm volatile("cp.async.cg.shared.global [%0], [%1], 16;" :: "r"(dst), "l"(src) : "memory")
#define CP_COMMIT() asm volatile("cp.async.commit_group;" ::: "memory")
#define CP_WAIT_0() asm volatile("cp.async.wait_group 0;" ::: "memory")

#define LDSM4(r0, r1, r2, r3, addr) \
    asm volatile("ldmatrix.sync.aligned.m8n8.x4.shared.b16 {%0,%1,%2,%3}, [%4];" \
        : "=r"(r0), "=r"(r1), "=r"(r2), "=r"(r3) : "r"(addr))

#define LDSM4T(r0, r1, r2, r3, addr) \
    asm volatile("ldmatrix.sync.aligned.m8n8.x4.trans.shared.b16 {%0,%1,%2,%3}, [%4];" \
        : "=r"(r0), "=r"(r1), "=r"(r2), "=r"(r3) : "r"(addr))

#define MMA16816(d, a, b0, b1) \
    asm volatile("mma.sync.aligned.m16n8k16.row.col.f32.f16.f16.f32 " \
        "{%0,%1,%2,%3}, {%4,%5,%6,%7}, {%8,%9}, {%0,%1,%2,%3};" \
        : "+f"((d)[0]), "+f"((d)[1]), "+f"((d)[2]), "+f"((d)[3]) \
        : "r"((a)[0]), "r"((a)[1]), "r"((a)[2]), "r"((a)[3]), "r"(b0), "r"(b1))

// ==================== prep: converts + rope table ====================
__device__ __forceinline__ void conv4(const float* __restrict__ src,
                                      __half* __restrict__ hi, int i) {
    float4 x = ((const float4*)src)[i];
    __half2* hp = (__half2*)(hi + i * 4);
    hp[0] = __half2(__float2half_rn(x.x), __float2half_rn(x.y));
    hp[1] = __half2(__float2half_rn(x.z), __float2half_rn(x.w));
}

#define WQ4 (DMODEL*DMODEL/4)
#define WK4 (KVD*DMODEL/4)
#define X4  (SEQ*DMODEL/4)
#define CONV_END (2*WQ4 + 2*WK4 + X4)
#define TOTAL_PREP (CONV_END + SEQ*32)
__global__ void prep_kernel(const float* __restrict__ Wq, const float* __restrict__ Wk,
                            const float* __restrict__ Wv, const float* __restrict__ Wo,
                            const float* __restrict__ x, const int* __restrict__ start_pos,
                            __half* __restrict__ qh, __half* __restrict__ kh,
                            __half* __restrict__ vh, __half* __restrict__ oh,
                            __half* __restrict__ xh) {
    int i = blockIdx.x * blockDim.x + threadIdx.x;
    if (i < WQ4)                     { conv4(Wq, qh, i); return; }
    if (i < WQ4 + WK4)               { conv4(Wk, kh, i - WQ4); return; }
    if (i < WQ4 + 2*WK4)             { conv4(Wv, vh, i - WQ4 - WK4); return; }
    if (i < 2*WQ4 + 2*WK4)           { conv4(Wo, oh, i - WQ4 - 2*WK4); return; }
    if (i < CONV_END)                { conv4(x, xh, i - 2*WQ4 - 2*WK4); return; }
    if (i >= TOTAL_PREP) return;
    int idx = i - CONV_END;
    int t = idx >> 5, j = idx & 31;
    const double PI = 3.14159265358979323846;
    double e = (double)(2 * j) / 64.0;
    double invf = pow(500000.0, -e);
    double wavelen = 2.0 * PI / invf;
    double inv;
    if (wavelen > 8192.0)      inv = invf / 32.0;
    else if (wavelen < 2048.0) inv = invf;
    else {
        double smooth = (8192.0 / wavelen - 1.0) / 3.0;
        inv = (1.0 - smooth) * (invf / 32.0) + smooth * invf;
    }
    float angle = (float)(start_pos[0] + t) * (float)inv;
    g_cos[idx] = (float)cos((double)angle);
    g_sin[idx] = (float)sin((double)angle);
}

// ==================== HMMA fp16 GEMM, split-K=2, fp16 partial out ====================
#define BK 32
#define ASTRH 40
#define TILEB (128 * ASTRH * 2)     // 10240 bytes
#define GSMEM (TILEB * 4)           // 2 stages x 2 tiles = 40960

__global__ void __launch_bounds__(256, 2) gemm_qkv(
    const __half* __restrict__ Ahi,
    const __half* __restrict__ B0h,
    __half* __restrict__ C0a, __half* __restrict__ C0b, int N0, int nx0,
    const __half* __restrict__ B1h,
    __half* __restrict__ C1a, __half* __restrict__ C1b, int N1, int nx1,
    const __half* __restrict__ B2h,
    __half* __restrict__ C2a, __half* __restrict__ C2b, int N2,
    int K, int Khalf) {
    extern __shared__ __half gsm[];
    const int bx = blockIdx.x;
    const int z = blockIdx.z;
    const __half *Bh; __half* C; int Nc, bnl;
    if (bx < nx0)            { Bh = B0h; C = z ? C0b : C0a; Nc = N0; bnl = bx * 128; }
    else if (bx < nx0 + nx1) { Bh = B1h; C = z ? C1b : C1a; Nc = N1; bnl = (bx - nx0) * 128; }
    else                     { Bh = B2h; C = z ? C2b : C2a; Nc = N2; bnl = (bx - nx0 - nx1) * 128; }
    const int koff = z * Khalf;

    const int tid = threadIdx.x;
    const int wid = tid >> 5, lane = tid & 31;
    const int wm = (wid & 1) * 64;
    const int wn = (wid >> 1) * 32;
    const int bm = blockIdx.y * 128;
    const int lr = lane & 15, lc = lane >> 4;

    uint32_t sbu = smem_u32(gsm);
    const int r0_ = tid >> 2, r1_ = r0_ + 64;
    const int pp = (tid & 3) * 8;

    float acc[4][4][4];
#pragma unroll
    for (int a = 0; a < 4; a++)
#pragma unroll
        for (int b = 0; b < 4; b++)
#pragma unroll
            for (int c = 0; c < 4; c++) acc[a][b][c] = 0.f;

#define LOADCHUNK(st, k0) do {                                                  \
    uint32_t _b = sbu + (st) * (2 * TILEB);                                     \
    CP_ASYNC16(_b + (r0_ * ASTRH + pp) * 2,                                     \
               Ahi + (size_t)(bm + r0_) * K + (k0) + pp);                       \
    CP_ASYNC16(_b + (r1_ * ASTRH + pp) * 2,                                     \
               Ahi + (size_t)(bm + r1_) * K + (k0) + pp);                       \
    CP_ASYNC16(_b + TILEB + (r0_ * ASTRH + pp) * 2,                             \
               Bh + (size_t)(bnl + r0_) * K + (k0) + pp);                       \
    CP_ASYNC16(_b + TILEB + (r1_ * ASTRH + pp) * 2,                             \
               Bh + (size_t)(bnl + r1_) * K + (k0) + pp);                       \
} while (0)

    const int kiters = Khalf / BK;
    LOADCHUNK(0, koff);
    CP_COMMIT();

    for (int i = 0; i < kiters; i++) {
        int s = i & 1;
        CP_WAIT_0();
        __syncthreads();
        if (i + 1 < kiters) {
            LOADCHUNK(s ^ 1, koff + (i + 1) * BK);
            CP_COMMIT();
        }

        uint32_t base = sbu + s * (2 * TILEB);
#pragma unroll
        for (int k16 = 0; k16 < 2; k16++) {
            int koff16 = k16 * 16 + lc * 8;
            uint32_t aH[4][4], bH[2][4];
#pragma unroll
            for (int mt = 0; mt < 4; mt++) {
                uint32_t adr = base + ((wm + mt * 16 + lr) * ASTRH + koff16) * 2;
                LDSM4(aH[mt][0], aH[mt][1], aH[mt][2], aH[mt][3], adr);
            }
#pragma unroll
            for (int p = 0; p < 2; p++) {
                uint32_t adr = base + TILEB + ((wn + p * 16 + lr) * ASTRH + koff16) * 2;
                LDSM4(bH[p][0], bH[p][1], bH[p][2], bH[p][3], adr);
            }
#pragma unroll
            for (int mt = 0; mt < 4; mt++)
#pragma unroll
                for (int nt = 0; nt < 4; nt++) {
                    int p = nt >> 1, w = nt & 1;
                    MMA16816(acc[mt][nt], aH[mt], bH[p][w], bH[p][w + 2]);
                }
        }
    }

    int er = lane >> 2, ec = (lane & 3) * 2;
#pragma unroll
    for (int mt = 0; mt < 4; mt++) {
#pragma unroll
        for (int nt = 0; nt < 4; nt++) {
            int r = bm + wm + mt * 16 + er;
            int c = bnl + wn + nt * 8 + ec;
            *(__half2*)&C[(size_t)r * Nc + c] =
                __floats2half2_rn(acc[mt][nt][0], acc[mt][nt][1]);
            *(__half2*)&C[(size_t)(r + 8) * Nc + c] =
                __floats2half2_rn(acc[mt][nt][2], acc[mt][nt][3]);
        }
    }
}

// ==================== partial-add + RoPE + convert (fp16 in/out) ====================
#define ROPE_TOTAL (SEQ * 40 * 32)
#define V4 (SEQ*KVD/4)
__global__ void rope_conv_all_kernel(const __half* __restrict__ q0, const __half* __restrict__ q1,
                                     const __half* __restrict__ k0, const __half* __restrict__ k1,
                                     const __half* __restrict__ v0, const __half* __restrict__ v1,
                                     __half* __restrict__ qhi, __half* __restrict__ khi,
                                     __half* __restrict__ vhi) {
    int idx = blockIdx.x * blockDim.x + threadIdx.x;
    if (idx < ROPE_TOTAL) {
        int j = idx & 31;
        int hh = (idx >> 5) % 40;
        int t = idx / (32 * 40);
        float c = g_cos[t * 32 + j];
        float s = g_sin[t * 32 + j];
        if (hh < NH) {
            size_t off = (size_t)t * DMODEL + hh * 64 + j;
            float x1 = __half2float(q0[off])      + __half2float(q1[off]);
            float x2 = __half2float(q0[off + 32]) + __half2float(q1[off + 32]);
            qhi[off]      = __float2half_rn(x1 * c - x2 * s);
            qhi[off + 32] = __float2half_rn(x2 * c + x1 * s);
        } else {
            size_t off = (size_t)t * KVD + (hh - NH) * 64 + j;
            float x1 = __half2float(k0[off])      + __half2float(k1[off]);
            float x2 = __half2float(k0[off + 32]) + __half2float(k1[off + 32]);
            khi[off]      = __float2half_rn(x1 * c - x2 * s);
            khi[off + 32] = __float2half_rn(x2 * c + x1 * s);
        }
    } else {
        int i = idx - ROPE_TOTAL;
        if (i >= V4) return;
        const __half2* a2 = (const __half2*)v0 + i * 2;
        const __half2* b2 = (const __half2*)v1 + i * 2;
        float2 a0 = __half22float2(a2[0]), a1 = __half22float2(a2[1]);
        float2 b0 = __half22float2(b2[0]), b1 = __half22float2(b2[1]);
        __half2* hp = (__half2*)(vhi + i * 4);
        hp[0] = __floats2half2_rn(a0.x + b0.x, a0.y + b0.y);
        hp[1] = __floats2half2_rn(a1.x + b1.x, a1.y + b1.y);
    }
}

// ==================== HMMA flash attention (1-term) ====================
#define FATR 72
#define FTILE (64 * FATR * 2)
#define FLASH_SMEM (FTILE * 5)   // Qh + 2 stages x (Kh, Vh)

__global__ void __launch_bounds__(128) flash_hmma(
    const __half* __restrict__ qhi,
    const __half* __restrict__ khi,
    const __half* __restrict__ vhi,
    __half* __restrict__ chi) {
    extern __shared__ __half fsm[];
    const int h  = blockIdx.x;
    const int qb = gridDim.y - 1 - blockIdx.y;
    const int g  = h >> 2;
    const int tid = threadIdx.x;
    const int wid = tid >> 5, lane = tid & 31;
    const int wm = wid * 16;
    const int er = lane >> 2, ec = (lane & 3) * 2;
    const int lr = lane & 15, lc = lane >> 4;

    uint32_t sb = smem_u32(fsm);
    uint32_t sQh = sb;

#pragma unroll
    for (int l = 0; l < 4; l++) {
        int c = tid + l * 128;
        int row = c >> 3, cc = c & 7;
        size_t off = (size_t)(qb * 64 + row) * DMODEL + h * 64 + cc * 8;
        CP_ASYNC16(sQh + row * FATR * 2 + cc * 16, qhi + off);
    }
#define KV_LOAD(kb_, st_) do {                                                  \
    uint32_t base = sb + FTILE + (st_) * 2 * FTILE;                             \
    _Pragma("unroll")                                                           \
    for (int l = 0; l < 4; l++) {                                               \
        int c = tid + l * 128;                                                  \
        int row = c >> 3, cc = c & 7;                                           \
        size_t off = (size_t)((kb_) * 64 + row) * KVD + g * 64 + cc * 8;        \
        uint32_t d = row * FATR * 2 + cc * 16;                                  \
        CP_ASYNC16(base + d, khi + off);                                        \
        CP_ASYNC16(base + FTILE + d, vhi + off);                                \
    }                                                                           \
} while (0)

    KV_LOAD(0, 0);
    CP_COMMIT();

    uint32_t aQh[4][4];
    float oacc[8][4];
    float mi0 = -INFINITY, mi1 = -INFINITY, li0 = 0.f, li1 = 0.f;
#pragma unroll
    for (int nt = 0; nt < 8; nt++)
#pragma unroll
        for (int j = 0; j < 4; j++) oacc[nt][j] = 0.f;

    for (int kb = 0; kb <= qb; kb++) {
        int stage = kb & 1;
        CP_WAIT_0();
        __syncthreads();
        if (kb < qb) {
            KV_LOAD(kb + 1, stage ^ 1);
            CP_COMMIT();
        }

        if (kb == 0) {
#pragma unroll
            for (int k16 = 0; k16 < 4; k16++) {
                uint32_t ah = sQh + ((wm + lr) * FATR + k16 * 16 + lc * 8) * 2;
                LDSM4(aQh[k16][0], aQh[k16][1], aQh[k16][2], aQh[k16][3], ah);
            }
        }

        uint32_t base = sb + FTILE + stage * 2 * FTILE;
        uint32_t sKh = base, sVh = base + FTILE;

        float sacc[8][4];
#pragma unroll
        for (int nt = 0; nt < 8; nt++)
#pragma unroll
            for (int j = 0; j < 4; j++) sacc[nt][j] = 0.f;

#pragma unroll
        for (int k16 = 0; k16 < 4; k16++) {
            uint32_t bh[4][4];
#pragma unroll
            for (int p = 0; p < 4; p++) {
                uint32_t adr = sKh + ((p * 16 + lr) * FATR + k16 * 16 + lc * 8) * 2;
                LDSM4(bh[p][0], bh[p][1], bh[p][2], bh[p][3], adr);
            }
#pragma unroll
            for (int nt = 0; nt < 8; nt++) {
                int p = nt >> 1, w = nt & 1;
                MMA16816(sacc[nt], aQh[k16], bh[p][w], bh[p][w + 2]);
            }
        }

        if (kb == qb) {
#pragma unroll
            for (int nt = 0; nt < 8; nt++) {
                int c0 = nt * 8 + ec;
                sacc[nt][0] = (c0     <= wm + er)     ? sacc[nt][0] * 0.125f : -INFINITY;
                sacc[nt][1] = (c0 + 1 <= wm + er)     ? sacc[nt][1] * 0.125f : -INFINITY;
                sacc[nt][2] = (c0     <= wm + er + 8) ? sacc[nt][2] * 0.125f : -INFINITY;
                sacc[nt][3] = (c0 + 1 <= wm + er + 8) ? sacc[nt][3] * 0.125f : -INFINITY;
            }
        } else {
#pragma unroll
            for (int nt = 0; nt < 8; nt++)
#pragma unroll
                for (int j = 0; j < 4; j++) sacc[nt][j] *= 0.125f;
        }

        float mx0 = -INFINITY, mx1 = -INFINITY;
#pragma unroll
        for (int nt = 0; nt < 8; nt++) {
            mx0 = fmaxf(mx0, fmaxf(sacc[nt][0], sacc[nt][1]));
            mx1 = fmaxf(mx1, fmaxf(sacc[nt][2], sacc[nt][3]));
        }
#pragma unroll
        for (int off = 1; off < 4; off <<= 1) {
            mx0 = fmaxf(mx0, __shfl_xor_sync(0xffffffffu, mx0, off));
            mx1 = fmaxf(mx1, __shfl_xor_sync(0xffffffffu, mx1, off));
        }
        float mn0 = fmaxf(mi0, mx0), mn1 = fmaxf(mi1, mx1);
        float sum0 = 0.f, sum1 = 0.f;
#pragma unroll
        for (int nt = 0; nt < 8; nt++) {
            sacc[nt][0] = __expf(sacc[nt][0] - mn0);
            sacc[nt][1] = __expf(sacc[nt][1] - mn0);
            sacc[nt][2] = __expf(sacc[nt][2] - mn1);
            sacc[nt][3] = __expf(sacc[nt][3] - mn1);
            sum0 += sacc[nt][0] + sacc[nt][1];
            sum1 += sacc[nt][2] + sacc[nt][3];
        }
#pragma unroll
        for (int off = 1; off < 4; off <<= 1) {
            sum0 += __shfl_xor_sync(0xffffffffu, sum0, off);
            sum1 += __shfl_xor_sync(0xffffffffu, sum1, off);
        }
        float sc0 = __expf(mi0 - mn0), sc1 = __expf(mi1 - mn1);
        li0 = li0 * sc0 + sum0; li1 = li1 * sc1 + sum1;
        mi0 = mn0; mi1 = mn1;
#pragma unroll
        for (int nt = 0; nt < 8; nt++) {
            oacc[nt][0] *= sc0; oacc[nt][1] *= sc0;
            oacc[nt][2] *= sc1; oacc[nt][3] *= sc1;
        }

#pragma unroll
        for (int k16 = 0; k16 < 4; k16++) {
            uint32_t ph[4];
#pragma unroll
            for (int half16 = 0; half16 < 2; half16++) {
                int st = 2 * k16 + half16;
                __half2 h01 = __floats2half2_rn(sacc[st][0], sacc[st][1]);
                __half2 h23 = __floats2half2_rn(sacc[st][2], sacc[st][3]);
                ph[half16 * 2]     = *(uint32_t*)&h01;
                ph[half16 * 2 + 1] = *(uint32_t*)&h23;
            }
            uint32_t bvh[4][4];
#pragma unroll
            for (int p = 0; p < 4; p++) {
                uint32_t adr = sVh + ((k16 * 16 + lr) * FATR + p * 16 + lc * 8) * 2;
                LDSM4T(bvh[p][0], bvh[p][1], bvh[p][2], bvh[p][3], adr);
            }
#pragma unroll
            for (int nt = 0; nt < 8; nt++) {
                int p = nt >> 1, w = (nt & 1) * 2;
                MMA16816(oacc[nt], ph, bvh[p][w], bvh[p][w + 1]);
            }
        }
    }

    float inv0 = 1.0f / li0, inv1 = 1.0f / li1;
    int r0g = qb * 64 + wm + er, r1g = r0g + 8;
#pragma unroll
    for (int nt = 0; nt < 8; nt++) {
        int c = h * 64 + nt * 8 + ec;
        __half2 h0 = __floats2half2_rn(oacc[nt][0] * inv0, oacc[nt][1] * inv0);
        __half2 h1 = __floats2half2_rn(oacc[nt][2] * inv1, oacc[nt][3] * inv1);
        *(__half2*)&chi[(size_t)r0g * DMODEL + c] = h0;
        *(__half2*)&chi[(size_t)r1g * DMODEL + c] = h1;
    }
}

// ==================== O-projection GEMM (fp32 out) ====================
__global__ void __launch_bounds__(256, 2) gemm_o(
    const __half* __restrict__ Ahi,
    const __half* __restrict__ Bh,
    float* __restrict__ C, int N, int K) {
    extern __shared__ __half gsm[];
    const int bnl = blockIdx.x * 128;

    const int tid = threadIdx.x;
    const int wid = tid >> 5, lane = tid & 31;
    const int wm = (wid & 1) * 64;
    const int wn = (wid >> 1) * 32;
    const int bm = blockIdx.y * 128;
    const int lr = lane & 15, lc = lane >> 4;

    uint32_t sbu = smem_u32(gsm);
    const int r0_ = tid >> 2, r1_ = r0_ + 64;
    const int pp = (tid & 3) * 8;

    float acc[4][4][4];
#pragma unroll
    for (int a = 0; a < 4; a++)
#pragma unroll
        for (int b = 0; b < 4; b++)
#pragma unroll
            for (int c = 0; c < 4; c++) acc[a][b][c] = 0.f;

    const int kiters = K / BK;
    LOADCHUNK(0, 0);
    CP_COMMIT();

    for (int i = 0; i < kiters; i++) {
        int s = i & 1;
        CP_WAIT_0();
        __syncthreads();
        if (i + 1 < kiters) {
            LOADCHUNK(s ^ 1, (i + 1) * BK);
            CP_COMMIT();
        }

        uint32_t base = sbu + s * (2 * TILEB);
#pragma unroll
        for (int k16 = 0; k16 < 2; k16++) {
            int koff16 = k16 * 16 + lc * 8;
            uint32_t aH[4][4], bH[2][4];
#pragma unroll
            for (int mt = 0; mt < 4; mt++) {
                uint32_t adr = base + ((wm + mt * 16 + lr) * ASTRH + koff16) * 2;
                LDSM4(aH[mt][0], aH[mt][1], aH[mt][2], aH[mt][3], adr);
            }
#pragma unroll
            for (int p = 0; p < 2; p++) {
                uint32_t adr = base + TILEB + ((wn + p * 16 + lr) * ASTRH + koff16) * 2;
                LDSM4(bH[p][0], bH[p][1], bH[p][2], bH[p][3], adr);
            }
#pragma unroll
            for (int mt = 0; mt < 4; mt++)
#pragma unroll
                for (int nt = 0; nt < 4; nt++) {
                    int p = nt >> 1, w = nt & 1;
                    MMA16816(acc[mt][nt], aH[mt], bH[p][w], bH[p][w + 2]);
                }
        }
    }

    int er = lane >> 2, ec = (lane & 3) * 2;
#pragma unroll
    for (int mt = 0; mt < 4; mt++) {
#pragma unroll
        for (int nt = 0; nt < 4; nt++) {
            int r = bm + wm + mt * 16 + er;
            int c = bnl + wn + nt * 8 + ec;
            *(float2*)&C[(size_t)r * N + c]       = make_float2(acc[mt][nt][0], acc[mt][nt][1]);
            *(float2*)&C[(size_t)(r + 8) * N + c] = make_float2(acc[mt][nt][2], acc[mt][nt][3]);
        }
    }
}

// -------------------- launch --------------------
extern "C" void kernel_launch(void* const* d_in, const int* in_sizes, int n_in,
                              void* d_out, int out_size) {
    const float* x  = (const float*)d_in[0];
    const float* Wq = (const float*)d_in[1];
    const float* Wk = (const float*)d_in[2];
    const float* Wv = (const float*)d_in[3];
    const float* Wo = (const float*)d_in[4];
    const int* start_pos = (const int*)d_in[5];
    float* out = (float*)d_out;

    __half *xhi, *wqhi, *wkhi, *wvhi, *wohi;
    __half *chi, *qh, *kh, *vh;
    __half *qp0, *qp1, *kp0, *kp1, *vp0, *vp1;
    cudaGetSymbolAddress((void**)&xhi, g_xhi);
    cudaGetSymbolAddress((void**)&wqhi, g_wqhi);
    cudaGetSymbolAddress((void**)&wkhi, g_wkhi);
    cudaGetSymbolAddress((void**)&wvhi, g_wvhi);
    cudaGetSymbolAddress((void**)&wohi, g_wohi);
    cudaGetSymbolAddress((void**)&chi, g_chi);
    cudaGetSymbolAddress((void**)&qh, g_qh);
    cudaGetSymbolAddress((void**)&kh, g_kh);
    cudaGetSymbolAddress((void**)&vh, g_vh);
    cudaGetSymbolAddress((void**)&qp0, g_qp0);  cudaGetSymbolAddress((void**)&qp1, g_qp1);
    cudaGetSymbolAddress((void**)&kp0, g_kp0);  cudaGetSymbolAddress((void**)&kp1, g_kp1);
    cudaGetSymbolAddress((void**)&vp0, g_vp0);  cudaGetSymbolAddress((void**)&vp1, g_vp1);

    cudaFuncSetAttribute(gemm_qkv, cudaFuncAttributeMaxDynamicSharedMemorySize, GSMEM);
    cudaFuncSetAttribute(gemm_o, cudaFuncAttributeMaxDynamicSharedMemorySize, GSMEM);
    cudaFuncSetAttribute(flash_hmma, cudaFuncAttributeMaxDynamicSharedMemorySize,
                         FLASH_SMEM);

    // 0: converts (4 weights + x) + rope table
    prep_kernel<<<(TOTAL_PREP + 255) / 256, 256>>>(
        Wq, Wk, Wv, Wo, x, start_pos, wqhi, wkhi, wvhi, wohi, xhi);
    // 1: fused Q/K/V projection, split-K=2, fp16 partials
    gemm_qkv<<<dim3(24, SEQ/128, 2), 256, GSMEM>>>(
        xhi,
        wqhi, qp0, qp1, DMODEL, 16,
        wkhi, kp0, kp1, KVD, 4,
        wvhi, vp0, vp1, KVD,
        DMODEL, DMODEL/2);
    // 2: partial-add + rope + convert
    rope_conv_all_kernel<<<(ROPE_TOTAL + V4 + 255) / 256, 256>>>(
        qp0, qp1, kp0, kp1, vp0, vp1, qh, kh, vh);
    // 3: flash attention (ncu sampling slot)
    flash_hmma<<<dim3(NH, SEQ / 64), 128, FLASH_SMEM>>>(qh, kh, vh, chi);
    // 4: O projection -> fp32 out
    gemm_o<<<dim3(16, SEQ / 128), 256, GSMEM>>>(chi, wohi, out, DMODEL, DMODEL);
}